// round 7
// baseline (speedup 1.0000x reference)
#include <cuda_runtime.h>

// SpikeFP32LayerNorm: row-wise LayerNorm (no affine) over 8192 rows x 4096 fp32.
// Converged configuration: 256 threads/CTA, one row/CTA, 4x float4 per thread
// (MLP_p1=4 — measured sweet spot: MLP=2 -> 38.2us, MLP=4 -> 36.0us,
// MLP=8 -> 36.2us), 8-warp two-stage reduction, rsqrt + 1 NR polish.
// Streaming hints on BOTH directions (touch-once data; L2 as staging only).
// Workload sits at the mixed read/write HBM wall (~74% of 8 TB/s spec).

#define ROWS  8192
#define NCOLS 4096
#define TPB   256            // 8 warps; 4x float4 per thread

__global__ __launch_bounds__(TPB, 6)
void spike_ln_kernel(const float* __restrict__ x, float* __restrict__ out) {
    const int tid = threadIdx.x;
    const int row = blockIdx.x;
    const float4* __restrict__ xin =
        reinterpret_cast<const float4*>(x + (size_t)row * NCOLS);
    float4* __restrict__ xout =
        reinterpret_cast<float4*>(out + (size_t)row * NCOLS);

    // Four independent 128-bit evict-first loads per thread (coalesced)
    float4 v0 = __ldcs(&xin[tid]);
    float4 v1 = __ldcs(&xin[tid + TPB]);
    float4 v2 = __ldcs(&xin[tid + 2 * TPB]);
    float4 v3 = __ldcs(&xin[tid + 3 * TPB]);

    float s  = ((v0.x + v0.y) + (v0.z + v0.w)) + ((v1.x + v1.y) + (v1.z + v1.w))
             + ((v2.x + v2.y) + (v2.z + v2.w)) + ((v3.x + v3.y) + (v3.z + v3.w));
    float sq = v0.x * v0.x + v0.y * v0.y + v0.z * v0.z + v0.w * v0.w
             + v1.x * v1.x + v1.y * v1.y + v1.z * v1.z + v1.w * v1.w
             + v2.x * v2.x + v2.y * v2.y + v2.z * v2.z + v2.w * v2.w
             + v3.x * v3.x + v3.y * v3.y + v3.z * v3.z + v3.w * v3.w;

    // Warp reduction of both accumulators
    #pragma unroll
    for (int off = 16; off > 0; off >>= 1) {
        s  += __shfl_xor_sync(0xFFFFFFFFu, s,  off);
        sq += __shfl_xor_sync(0xFFFFFFFFu, sq, off);
    }

    __shared__ float ssum[8];
    __shared__ float ssq[8];
    __shared__ float s_mean, s_rstd;

    const int wid = tid >> 5;
    const int lid = tid & 31;
    if (lid == 0) { ssum[wid] = s; ssq[wid] = sq; }
    __syncthreads();

    if (wid == 0) {
        float ts  = (lid < 8) ? ssum[lid] : 0.0f;
        float tsq = (lid < 8) ? ssq[lid]  : 0.0f;
        #pragma unroll
        for (int off = 4; off > 0; off >>= 1) {
            ts  += __shfl_xor_sync(0xFFFFFFFFu, ts,  off);
            tsq += __shfl_xor_sync(0xFFFFFFFFu, tsq, off);
        }
        if (lid == 0) {
            const float inv_n = 1.0f / (float)NCOLS;
            float mean = ts * inv_n;
            float var  = fmaxf(tsq * inv_n - mean * mean, 0.0f);
            float vpe  = var + 1e-6f;
            float y = rsqrtf(vpe);
            y = 0.5f * y * (3.0f - vpe * (y * y));   // one NR polish
            s_mean = mean;
            s_rstd = y;
        }
    }
    __syncthreads();

    const float mean = s_mean;
    const float rstd = s_rstd;

    float4 o0, o1, o2, o3;
    o0.x = (v0.x - mean) * rstd;  o0.y = (v0.y - mean) * rstd;
    o0.z = (v0.z - mean) * rstd;  o0.w = (v0.w - mean) * rstd;
    o1.x = (v1.x - mean) * rstd;  o1.y = (v1.y - mean) * rstd;
    o1.z = (v1.z - mean) * rstd;  o1.w = (v1.w - mean) * rstd;
    o2.x = (v2.x - mean) * rstd;  o2.y = (v2.y - mean) * rstd;
    o2.z = (v2.z - mean) * rstd;  o2.w = (v2.w - mean) * rstd;
    o3.x = (v3.x - mean) * rstd;  o3.y = (v3.y - mean) * rstd;
    o3.z = (v3.z - mean) * rstd;  o3.w = (v3.w - mean) * rstd;

    __stcs(&xout[tid],           o0);
    __stcs(&xout[tid + TPB],     o1);
    __stcs(&xout[tid + 2 * TPB], o2);
    __stcs(&xout[tid + 3 * TPB], o3);
}

extern "C" void kernel_launch(void* const* d_in, const int* in_sizes, int n_in,
                              void* d_out, int out_size) {
    const float* x = (const float*)d_in[0];
    float* out = (float*)d_out;
    spike_ln_kernel<<<ROWS, TPB>>>(x, out);
}

// round 8
// speedup vs baseline: 1.0059x; 1.0059x over previous
#include <cuda_runtime.h>

// SpikeFP32LayerNorm: row-wise LayerNorm (no affine) over 8192 rows x 4096 fp32.
// Converged configuration: 256 threads/CTA, one row/CTA, 4x float4 per thread
// (MLP sweep: 2 -> 38.2us, 4 -> 36.0us, 8 -> 36.2us), two-stage shuffle+smem
// reduction, rsqrt + 1 NR polish, evict-first streaming on both directions
// (ldcs/stcs: 36.0 -> 35.7us). This round: full 8-CTA/SM residency hint
// (regs=32 exactly fits 64K regs/SM) for max bytes-in-flight.
// Workload sits at the mixed read/write HBM wall (~74% of 8 TB/s spec).

#define ROWS  8192
#define NCOLS 4096
#define TPB   256            // 8 warps; 4x float4 per thread

__global__ __launch_bounds__(TPB, 8)
void spike_ln_kernel(const float* __restrict__ x, float* __restrict__ out) {
    const int tid = threadIdx.x;
    const int row = blockIdx.x;
    const float4* __restrict__ xin =
        reinterpret_cast<const float4*>(x + (size_t)row * NCOLS);
    float4* __restrict__ xout =
        reinterpret_cast<float4*>(out + (size_t)row * NCOLS);

    // Four independent 128-bit evict-first loads per thread (coalesced)
    float4 v0 = __ldcs(&xin[tid]);
    float4 v1 = __ldcs(&xin[tid + TPB]);
    float4 v2 = __ldcs(&xin[tid + 2 * TPB]);
    float4 v3 = __ldcs(&xin[tid + 3 * TPB]);

    float s  = ((v0.x + v0.y) + (v0.z + v0.w)) + ((v1.x + v1.y) + (v1.z + v1.w))
             + ((v2.x + v2.y) + (v2.z + v2.w)) + ((v3.x + v3.y) + (v3.z + v3.w));
    float sq = v0.x * v0.x + v0.y * v0.y + v0.z * v0.z + v0.w * v0.w
             + v1.x * v1.x + v1.y * v1.y + v1.z * v1.z + v1.w * v1.w
             + v2.x * v2.x + v2.y * v2.y + v2.z * v2.z + v2.w * v2.w
             + v3.x * v3.x + v3.y * v3.y + v3.z * v3.z + v3.w * v3.w;

    // Warp reduction of both accumulators
    #pragma unroll
    for (int off = 16; off > 0; off >>= 1) {
        s  += __shfl_xor_sync(0xFFFFFFFFu, s,  off);
        sq += __shfl_xor_sync(0xFFFFFFFFu, sq, off);
    }

    __shared__ float ssum[8];
    __shared__ float ssq[8];
    __shared__ float s_mean, s_rstd;

    const int wid = tid >> 5;
    const int lid = tid & 31;
    if (lid == 0) { ssum[wid] = s; ssq[wid] = sq; }
    __syncthreads();

    if (wid == 0) {
        float ts  = (lid < 8) ? ssum[lid] : 0.0f;
        float tsq = (lid < 8) ? ssq[lid]  : 0.0f;
        #pragma unroll
        for (int off = 4; off > 0; off >>= 1) {
            ts  += __shfl_xor_sync(0xFFFFFFFFu, ts,  off);
            tsq += __shfl_xor_sync(0xFFFFFFFFu, tsq, off);
        }
        if (lid == 0) {
            const float inv_n = 1.0f / (float)NCOLS;
            float mean = ts * inv_n;
            float var  = fmaxf(tsq * inv_n - mean * mean, 0.0f);
            float vpe  = var + 1e-6f;
            float y = rsqrtf(vpe);
            y = 0.5f * y * (3.0f - vpe * (y * y));   // one NR polish
            s_mean = mean;
            s_rstd = y;
        }
    }
    __syncthreads();

    const float mean = s_mean;
    const float rstd = s_rstd;

    float4 o0, o1, o2, o3;
    o0.x = (v0.x - mean) * rstd;  o0.y = (v0.y - mean) * rstd;
    o0.z = (v0.z - mean) * rstd;  o0.w = (v0.w - mean) * rstd;
    o1.x = (v1.x - mean) * rstd;  o1.y = (v1.y - mean) * rstd;
    o1.z = (v1.z - mean) * rstd;  o1.w = (v1.w - mean) * rstd;
    o2.x = (v2.x - mean) * rstd;  o2.y = (v2.y - mean) * rstd;
    o2.z = (v2.z - mean) * rstd;  o2.w = (v2.w - mean) * rstd;
    o3.x = (v3.x - mean) * rstd;  o3.y = (v3.y - mean) * rstd;
    o3.z = (v3.z - mean) * rstd;  o3.w = (v3.w - mean) * rstd;

    __stcs(&xout[tid],           o0);
    __stcs(&xout[tid + TPB],     o1);
    __stcs(&xout[tid + 2 * TPB], o2);
    __stcs(&xout[tid + 3 * TPB], o3);
}

extern "C" void kernel_launch(void* const* d_in, const int* in_sizes, int n_in,
                              void* d_out, int out_size) {
    const float* x = (const float*)d_in[0];
    float* out = (float*)d_out;
    spike_ln_kernel<<<ROWS, TPB>>>(x, out);
}

// round 9
// speedup vs baseline: 1.0066x; 1.0007x over previous
#include <cuda_runtime.h>

// SpikeFP32LayerNorm: row-wise LayerNorm (no affine) over 8192 rows x 4096 fp32.
// Final converged configuration: 256 threads/CTA, one row/CTA, 4x float4 per
// thread (MLP sweep: 2 -> 38.2us, 4 -> 36.0us, 8 -> 36.2us), two-stage
// shuffle+smem reduction, rsqrt + 1 NR polish, evict-first streaming on both
// directions, 8-CTA/SM residency (regs=32 fills the 64K register file).
// Epilogue folded to single FFMAs: o = v*rstd + (-mean*rstd).
// Measured trajectory: 38.7 -> 35.5us; at the mixed R/W HBM wall (~75% spec).

#define ROWS  8192
#define NCOLS 4096
#define TPB   256            // 8 warps; 4x float4 per thread

__global__ __launch_bounds__(TPB, 8)
void spike_ln_kernel(const float* __restrict__ x, float* __restrict__ out) {
    const int tid = threadIdx.x;
    const int row = blockIdx.x;
    const float4* __restrict__ xin =
        reinterpret_cast<const float4*>(x + (size_t)row * NCOLS);
    float4* __restrict__ xout =
        reinterpret_cast<float4*>(out + (size_t)row * NCOLS);

    // Four independent 128-bit evict-first loads per thread (coalesced)
    float4 v0 = __ldcs(&xin[tid]);
    float4 v1 = __ldcs(&xin[tid + TPB]);
    float4 v2 = __ldcs(&xin[tid + 2 * TPB]);
    float4 v3 = __ldcs(&xin[tid + 3 * TPB]);

    float s  = ((v0.x + v0.y) + (v0.z + v0.w)) + ((v1.x + v1.y) + (v1.z + v1.w))
             + ((v2.x + v2.y) + (v2.z + v2.w)) + ((v3.x + v3.y) + (v3.z + v3.w));
    float sq = v0.x * v0.x + v0.y * v0.y + v0.z * v0.z + v0.w * v0.w
             + v1.x * v1.x + v1.y * v1.y + v1.z * v1.z + v1.w * v1.w
             + v2.x * v2.x + v2.y * v2.y + v2.z * v2.z + v2.w * v2.w
             + v3.x * v3.x + v3.y * v3.y + v3.z * v3.z + v3.w * v3.w;

    // Warp reduction of both accumulators
    #pragma unroll
    for (int off = 16; off > 0; off >>= 1) {
        s  += __shfl_xor_sync(0xFFFFFFFFu, s,  off);
        sq += __shfl_xor_sync(0xFFFFFFFFu, sq, off);
    }

    __shared__ float ssum[8];
    __shared__ float ssq[8];
    __shared__ float s_rstd, s_nm;   // rstd and -mean*rstd

    const int wid = tid >> 5;
    const int lid = tid & 31;
    if (lid == 0) { ssum[wid] = s; ssq[wid] = sq; }
    __syncthreads();

    if (wid == 0) {
        float ts  = (lid < 8) ? ssum[lid] : 0.0f;
        float tsq = (lid < 8) ? ssq[lid]  : 0.0f;
        #pragma unroll
        for (int off = 4; off > 0; off >>= 1) {
            ts  += __shfl_xor_sync(0xFFFFFFFFu, ts,  off);
            tsq += __shfl_xor_sync(0xFFFFFFFFu, tsq, off);
        }
        if (lid == 0) {
            const float inv_n = 1.0f / (float)NCOLS;
            float mean = ts * inv_n;
            float var  = fmaxf(tsq * inv_n - mean * mean, 0.0f);
            float vpe  = var + 1e-6f;
            float y = rsqrtf(vpe);
            y = 0.5f * y * (3.0f - vpe * (y * y));   // one NR polish
            s_rstd = y;
            s_nm   = -mean * y;
        }
    }
    __syncthreads();

    const float rstd = s_rstd;
    const float nm   = s_nm;

    // Single-FFMA epilogue: o = v * rstd + nm
    float4 o0, o1, o2, o3;
    o0.x = fmaf(v0.x, rstd, nm);  o0.y = fmaf(v0.y, rstd, nm);
    o0.z = fmaf(v0.z, rstd, nm);  o0.w = fmaf(v0.w, rstd, nm);
    o1.x = fmaf(v1.x, rstd, nm);  o1.y = fmaf(v1.y, rstd, nm);
    o1.z = fmaf(v1.z, rstd, nm);  o1.w = fmaf(v1.w, rstd, nm);
    o2.x = fmaf(v2.x, rstd, nm);  o2.y = fmaf(v2.y, rstd, nm);
    o2.z = fmaf(v2.z, rstd, nm);  o2.w = fmaf(v2.w, rstd, nm);
    o3.x = fmaf(v3.x, rstd, nm);  o3.y = fmaf(v3.y, rstd, nm);
    o3.z = fmaf(v3.z, rstd, nm);  o3.w = fmaf(v3.w, rstd, nm);

    __stcs(&xout[tid],           o0);
    __stcs(&xout[tid + TPB],     o1);
    __stcs(&xout[tid + 2 * TPB], o2);
    __stcs(&xout[tid + 3 * TPB], o3);
}

extern "C" void kernel_launch(void* const* d_in, const int* in_sizes, int n_in,
                              void* d_out, int out_size) {
    const float* x = (const float*)d_in[0];
    float* out = (float*)d_out;
    spike_ln_kernel<<<ROWS, TPB>>>(x, out);
}